// round 4
// baseline (speedup 1.0000x reference)
#include <cuda_runtime.h>
#include <math.h>
#include <stdint.h>

#define B_  8192
#define D_  256
#define M_  10
#define H_  4
#define DK_ 64

// ---------------- scratch (device globals; no allocation allowed) ----------
__device__ float g_z   [B_*D_];        // z_t
__device__ float g_xp  [B_*3*D_];      // z_t @ gru_k + b0
__device__ float g_hp  [B_*3*D_];      // h_prev @ gru_rk + b1
__device__ float g_gru [B_*D_];        // gru_out
__device__ float g_q   [B_*D_];        // q
__device__ float g_k   [B_*M_*D_];     // k (81920 x 256)
__device__ float g_v   [B_*M_*D_];     // v
__device__ float g_ctxh[B_*D_];        // attention context heads
__device__ float g_ctx [B_*D_];        // context (pre/post LN, in place)
__device__ float g_ctxp[B_*D_];        // tanh(ctx_ln @ W_ctx + b)
__device__ float g_alph[B_*D_];        // gate

__device__ __forceinline__ float sigf(float x) { return 1.0f / (1.0f + expf(-x)); }

__device__ __forceinline__ uint32_t f2tf32(float f) {
    uint32_t u;
    asm("cvt.rna.tf32.f32 %0, %1;" : "=r"(u) : "f"(f));
    return u;
}

__device__ __forceinline__ void mma_tf32(float acc[4], const uint32_t a[4], const uint32_t b[2]) {
    asm volatile(
        "mma.sync.aligned.m16n8k8.row.col.f32.tf32.tf32.f32 "
        "{%0,%1,%2,%3}, {%4,%5,%6,%7}, {%8,%9}, {%0,%1,%2,%3};"
        : "+f"(acc[0]), "+f"(acc[1]), "+f"(acc[2]), "+f"(acc[3])
        : "r"(a[0]), "r"(a[1]), "r"(a[2]), "r"(a[3]), "r"(b[0]), "r"(b[1]));
}

// ---------------- tf32 tensor-core GEMM: C = epi(A @ W + bias) -------------
// A: (Mrows x K) row-major (if DUAL: A = cols [0,256), A2 = cols [256,K))
// W: (K x N) row-major, bias: (N), C row stride ldc.
// Block tile 128x64, BK=32, 256 threads (8 warps, 4x2), warp tile 32x32.
// EPI: 0 = identity, 1 = tanh, 2 = sigmoid
template<int EPI, bool DUAL>
__global__ __launch_bounds__(256)
void gemm_tf32(const float* __restrict__ A, const float* __restrict__ A2,
               const float* __restrict__ W, const float* __restrict__ bias,
               float* __restrict__ C, int N, int K, int ldc)
{
    const int BM = 128, BN = 64, BK = 32;
    __shared__ uint32_t As[BK][BM + 4];   // [k][m], tf32 bits
    __shared__ uint32_t Bs[BK][BN + 4];   // [k][n], tf32 bits

    const int bm   = blockIdx.y * BM;
    const int bn   = blockIdx.x * BN;
    const int tid  = threadIdx.x;
    const int lane = tid & 31;
    const int wid  = tid >> 5;
    const int wm   = (wid & 3) * 32;      // warp m-offset within block
    const int wn   = (wid >> 2) * 32;     // warp n-offset within block
    const int g    = lane >> 2;           // group id (0..7)
    const int q    = lane & 3;            // quad id  (0..3)

    float acc[2][4][4];                   // [m-tile][n-tile][frag]
    #pragma unroll
    for (int t = 0; t < 2; t++)
        #pragma unroll
        for (int j = 0; j < 4; j++)
            #pragma unroll
            for (int e = 0; e < 4; e++) acc[t][j][e] = 0.0f;

    for (int k0 = 0; k0 < K; k0 += BK) {
        // ---- load A tile (128 rows x 32 k), convert to tf32, transpose ----
        #pragma unroll
        for (int i = 0; i < 4; i++) {
            int idx = tid + i * 256;      // 1024 float4 slots
            int row = idx >> 3;
            int c4  = (idx & 7) * 4;
            int gk  = k0 + c4;
            float4 v;
            if (DUAL) {
                v = (gk < 256) ? *(const float4*)&A [(size_t)(bm + row) * 256 + gk]
                               : *(const float4*)&A2[(size_t)(bm + row) * 256 + gk - 256];
            } else {
                v = *(const float4*)&A[(size_t)(bm + row) * K + gk];
            }
            As[c4 + 0][row] = f2tf32(v.x);
            As[c4 + 1][row] = f2tf32(v.y);
            As[c4 + 2][row] = f2tf32(v.z);
            As[c4 + 3][row] = f2tf32(v.w);
        }
        // ---- load W tile (32 k x 64 n), convert to tf32 ----
        #pragma unroll
        for (int i = 0; i < 2; i++) {
            int idx = tid + i * 256;      // 512 float4 slots
            int row = idx >> 4;
            int c4  = (idx & 15) * 4;
            float4 v = *(const float4*)&W[(size_t)(k0 + row) * N + bn + c4];
            Bs[row][c4 + 0] = f2tf32(v.x);
            Bs[row][c4 + 1] = f2tf32(v.y);
            Bs[row][c4 + 2] = f2tf32(v.z);
            Bs[row][c4 + 3] = f2tf32(v.w);
        }
        __syncthreads();

        #pragma unroll
        for (int ks = 0; ks < BK; ks += 8) {
            uint32_t a[2][4];
            #pragma unroll
            for (int t = 0; t < 2; t++) {
                int r = wm + t * 16 + g;
                a[t][0] = As[ks + q    ][r];
                a[t][1] = As[ks + q    ][r + 8];
                a[t][2] = As[ks + q + 4][r];
                a[t][3] = As[ks + q + 4][r + 8];
            }
            uint32_t b[4][2];
            #pragma unroll
            for (int j = 0; j < 4; j++) {
                int c = wn + j * 8 + g;
                b[j][0] = Bs[ks + q    ][c];
                b[j][1] = Bs[ks + q + 4][c];
            }
            #pragma unroll
            for (int t = 0; t < 2; t++)
                #pragma unroll
                for (int j = 0; j < 4; j++)
                    mma_tf32(acc[t][j], a[t], b[j]);
        }
        __syncthreads();
    }

    // ---- epilogue: bias + activation, float2 stores ----
    #pragma unroll
    for (int t = 0; t < 2; t++) {
        #pragma unroll
        for (int j = 0; j < 4; j++) {
            int col = bn + wn + j * 8 + 2 * q;
            float b0 = bias[col], b1 = bias[col + 1];
            #pragma unroll
            for (int h = 0; h < 2; h++) {        // h=0 -> c0,c1 ; h=1 -> c2,c3
                int row = bm + wm + t * 16 + g + h * 8;
                float v0 = acc[t][j][2 * h]     + b0;
                float v1 = acc[t][j][2 * h + 1] + b1;
                if (EPI == 1) { v0 = tanhf(v0); v1 = tanhf(v1); }
                if (EPI == 2) { v0 = sigf(v0);  v1 = sigf(v1);  }
                *(float2*)&C[(size_t)row * ldc + col] = make_float2(v0, v1);
            }
        }
    }
}

// ---------------- GRU elementwise (keras reset_after=True) -----------------
__global__ void gru_kernel(const float* __restrict__ h_prev)
{
    int idx = blockIdx.x * blockDim.x + threadIdx.x;
    if (idx >= B_ * D_) return;
    int b = idx >> 8, d = idx & 255;
    const float* xp = g_xp + (size_t)b * 768;
    const float* hp = g_hp + (size_t)b * 768;
    float z  = sigf(xp[d]       + hp[d]);
    float r  = sigf(xp[256 + d] + hp[256 + d]);
    float hc = tanhf(xp[512 + d] + r * hp[512 + d]);
    float h  = h_prev[idx];
    g_gru[idx] = z * h + (1.0f - z) * hc;
}

// ---------------- attention: one warp per (b, h) ----------------------------
__global__ void attn_kernel()
{
    int gw   = (blockIdx.x * blockDim.x + threadIdx.x) >> 5;
    int lane = threadIdx.x & 31;
    if (gw >= B_ * H_) return;
    int b = gw >> 2;
    int h = gw & 3;

    const float* qp = g_q + (size_t)b * D_ + h * DK_;
    float q0 = qp[2 * lane], q1 = qp[2 * lane + 1];

    float sc[M_];
    #pragma unroll
    for (int m = 0; m < M_; m++) {
        const float* kp = g_k + ((size_t)b * M_ + m) * D_ + h * DK_;
        float p = q0 * kp[2 * lane] + q1 * kp[2 * lane + 1];
        #pragma unroll
        for (int o = 16; o > 0; o >>= 1) p += __shfl_xor_sync(0xffffffffu, p, o);
        sc[m] = p * 0.125f;
    }
    float mx = sc[0];
    #pragma unroll
    for (int m = 1; m < M_; m++) mx = fmaxf(mx, sc[m]);
    float sum = 0.0f;
    #pragma unroll
    for (int m = 0; m < M_; m++) { sc[m] = expf(sc[m] - mx); sum += sc[m]; }
    float inv = 1.0f / sum;

    float c0 = 0.0f, c1 = 0.0f;
    #pragma unroll
    for (int m = 0; m < M_; m++) {
        const float* vp = g_v + ((size_t)b * M_ + m) * D_ + h * DK_;
        float a = sc[m] * inv;
        c0 += a * vp[2 * lane];
        c1 += a * vp[2 * lane + 1];
    }
    float* cp = g_ctxh + (size_t)b * D_ + h * DK_;
    cp[2 * lane]     = c0;
    cp[2 * lane + 1] = c1;
}

// ---------------- LayerNorm (warp per row, D = 256) -------------------------
__device__ __forceinline__ void ln_row(const float* x8, int lane,
                                       const float* __restrict__ gm,
                                       const float* __restrict__ bt,
                                       float* __restrict__ yrow)
{
    float s = 0.0f, ss = 0.0f;
    #pragma unroll
    for (int i = 0; i < 8; i++) { s += x8[i]; ss += x8[i] * x8[i]; }
    #pragma unroll
    for (int o = 16; o > 0; o >>= 1) {
        s  += __shfl_xor_sync(0xffffffffu, s,  o);
        ss += __shfl_xor_sync(0xffffffffu, ss, o);
    }
    float mu  = s * (1.0f / 256.0f);
    float var = ss * (1.0f / 256.0f) - mu * mu;
    float inv = rsqrtf(var + 1e-3f);
    float out[8];
    #pragma unroll
    for (int i = 0; i < 8; i++) {
        int d = lane * 8 + i;
        out[i] = (x8[i] - mu) * inv * gm[d] + bt[d];
    }
    *(float4*)(yrow + lane * 8)     = make_float4(out[0], out[1], out[2], out[3]);
    *(float4*)(yrow + lane * 8 + 4) = make_float4(out[4], out[5], out[6], out[7]);
}

__global__ void ln_kernel(const float* __restrict__ x, const float* __restrict__ gm,
                          const float* __restrict__ bt, float* __restrict__ y)
{
    int w    = (blockIdx.x * blockDim.x + threadIdx.x) >> 5;
    int lane = threadIdx.x & 31;
    if (w >= B_) return;
    const float* row = x + (size_t)w * D_;
    float4 v0 = *(const float4*)(row + lane * 8);
    float4 v1 = *(const float4*)(row + lane * 8 + 4);
    float x8[8] = {v0.x, v0.y, v0.z, v0.w, v1.x, v1.y, v1.z, v1.w};
    ln_row(x8, lane, gm, bt, y + (size_t)w * D_);
}

__global__ void blend_ln_kernel(const float* __restrict__ gm,
                                const float* __restrict__ bt,
                                float* __restrict__ out)
{
    int w    = (blockIdx.x * blockDim.x + threadIdx.x) >> 5;
    int lane = threadIdx.x & 31;
    if (w >= B_) return;
    size_t base = (size_t)w * D_ + lane * 8;
    float x8[8];
    #pragma unroll
    for (int i = 0; i < 8; i++) {
        float a = g_alph[base + i];
        x8[i] = (1.0f - a) * g_gru[base + i] + a * g_ctxp[base + i];
    }
    ln_row(x8, lane, gm, bt, out + (size_t)w * D_);
}

// ---------------- memory shift: out_mem[b, 0:9D] = mem[b, D:10D] ------------
__global__ void memshift_kernel(const float* __restrict__ memflat,
                                float* __restrict__ outmem)
{
    const int per = (M_ - 1) * D_ / 4;   // 576 float4 per row
    int idx = blockIdx.x * blockDim.x + threadIdx.x;
    if (idx >= B_ * per) return;
    int b = idx / per, j = idx - b * per;
    const float4* src = (const float4*)(memflat + (size_t)b * (M_ * D_) + D_);
    float4*       dst = (float4*)(outmem + (size_t)b * (M_ * D_));
    dst[j] = src[j];
}

// ---------------- host ------------------------------------------------------
extern "C" void kernel_launch(void* const* d_in, const int* in_sizes, int n_in,
                              void* d_out, int out_size)
{
    const float* inputs    = (const float*)d_in[0];
    const float* h_prev    = (const float*)d_in[1];
    const float* memflat   = (const float*)d_in[2];
    const float* W_in      = (const float*)d_in[3];
    const float* b_in      = (const float*)d_in[4];
    const float* gru_k     = (const float*)d_in[5];
    const float* gru_rk    = (const float*)d_in[6];
    const float* gru_b     = (const float*)d_in[7];
    const float* Wq        = (const float*)d_in[8];
    const float* bq        = (const float*)d_in[9];
    const float* Wk        = (const float*)d_in[10];
    const float* bk        = (const float*)d_in[11];
    const float* Wv        = (const float*)d_in[12];
    const float* bv        = (const float*)d_in[13];
    const float* Wo        = (const float*)d_in[14];
    const float* bo        = (const float*)d_in[15];
    const float* g_attn    = (const float*)d_in[16];
    const float* beta_attn = (const float*)d_in[17];
    const float* g_out     = (const float*)d_in[18];
    const float* beta_out  = (const float*)d_in[19];
    const float* W_ctx     = (const float*)d_in[20];
    const float* b_ctx     = (const float*)d_in[21];
    const float* W_gate    = (const float*)d_in[22];
    const float* b_gate    = (const float*)d_in[23];
    const float* W_mem     = (const float*)d_in[24];
    const float* b_mem     = (const float*)d_in[25];
    float* out = (float*)d_out;

    float *zP, *xpP, *hpP, *gruP, *qP, *kP, *vP, *ctxhP, *ctxP, *ctxpP, *alphP;
    cudaGetSymbolAddress((void**)&zP,    g_z);
    cudaGetSymbolAddress((void**)&xpP,   g_xp);
    cudaGetSymbolAddress((void**)&hpP,   g_hp);
    cudaGetSymbolAddress((void**)&gruP,  g_gru);
    cudaGetSymbolAddress((void**)&qP,    g_q);
    cudaGetSymbolAddress((void**)&kP,    g_k);
    cudaGetSymbolAddress((void**)&vP,    g_v);
    cudaGetSymbolAddress((void**)&ctxhP, g_ctxh);
    cudaGetSymbolAddress((void**)&ctxP,  g_ctx);
    cudaGetSymbolAddress((void**)&ctxpP, g_ctxp);
    cudaGetSymbolAddress((void**)&alphP, g_alph);

    const dim3 blk(256);
    const dim3 gB (4, 64);     // 8192 x 256   (N=256 -> 4 blocks in x)
    const dim3 gB3(12, 64);    // 8192 x 768   (N=768 -> 12)
    const dim3 gGate(4, 64);   // 8192 x 256, K=512 (gate: N=256 -> 4!)
    const dim3 gKV(4, 640);    // 81920 x 256

    // K/V projections (independent, biggest) first
    gemm_tf32<0,false><<<gKV, blk>>>(memflat, nullptr, Wk, bk, kP, 256, 256, 256);
    gemm_tf32<0,false><<<gKV, blk>>>(memflat, nullptr, Wv, bv, vP, 256, 256, 256);

    // z_t, GRU
    gemm_tf32<0,false><<<gB,  blk>>>(inputs, nullptr, W_in,   b_in,        zP,  256, 256, 256);
    gemm_tf32<0,false><<<gB3, blk>>>(zP,     nullptr, gru_k,  gru_b,       xpP, 768, 256, 768);
    gemm_tf32<0,false><<<gB3, blk>>>(h_prev, nullptr, gru_rk, gru_b + 768, hpP, 768, 256, 768);
    gru_kernel<<<(B_ * D_ + 255) / 256, 256>>>(h_prev);

    // attention
    gemm_tf32<0,false><<<gB, blk>>>(gruP, nullptr, Wq, bq, qP, 256, 256, 256);
    attn_kernel<<<(B_ * H_ * 32 + 255) / 256, 256>>>();
    gemm_tf32<0,false><<<gB, blk>>>(ctxhP, nullptr, Wo, bo, ctxP, 256, 256, 256);
    ln_kernel<<<(B_ * 32 + 255) / 256, 256>>>(ctxP, g_attn, beta_attn, ctxP);

    // ctx_p, gate, blend+LN -> h_corr
    gemm_tf32<1,false><<<gB,    blk>>>(ctxP, nullptr, W_ctx,  b_ctx,  ctxpP, 256, 256, 256);
    gemm_tf32<2,true ><<<gGate, blk>>>(gruP, ctxpP,   W_gate, b_gate, alphP, 256, 512, 256);
    blend_ln_kernel<<<(B_ * 32 + 255) / 256, 256>>>(g_out, beta_out, out);

    // memory write: shifted copy + new entry in last slot
    memshift_kernel<<<(B_ * 576 + 255) / 256, 256>>>(memflat, out + B_ * D_);
    gemm_tf32<0,false><<<gB, blk>>>(zP, nullptr, W_mem, b_mem,
                                    out + B_ * D_ + (M_ - 1) * D_, 256, 256, M_ * D_);
}

// round 5
// speedup vs baseline: 1.0008x; 1.0008x over previous
#include <cuda_runtime.h>
#include <math.h>
#include <stdint.h>

#define B_  8192
#define D_  256
#define M_  10
#define H_  4
#define DK_ 64

// ---------------- scratch (device globals; no allocation allowed) ----------
__device__ float g_z   [B_*D_];        // z_t
__device__ float g_xp  [B_*3*D_];      // z_t @ gru_k + b0
__device__ float g_hp  [B_*3*D_];      // h_prev @ gru_rk + b1
__device__ float g_gru [B_*D_];        // gru_out
__device__ float g_q   [B_*D_];        // q
__device__ float g_k   [B_*M_*D_];     // k (81920 x 256)
__device__ float g_v   [B_*M_*D_];     // v
__device__ float g_ctxh[B_*D_];        // attention context heads
__device__ float g_ctx [B_*D_];        // context (pre/post LN, in place)
__device__ float g_ctxp[B_*D_];        // tanh(ctx_ln @ W_ctx + b)
__device__ float g_alph[B_*D_];        // gate

__device__ __forceinline__ float sigf(float x) { return 1.0f / (1.0f + expf(-x)); }

__device__ __forceinline__ uint32_t f2tf32(float f) {
    uint32_t u;
    asm("cvt.rna.tf32.f32 %0, %1;" : "=r"(u) : "f"(f));
    return u;
}

__device__ __forceinline__ void mma_tf32(float acc[4], const uint32_t a[4], const uint32_t b[2]) {
    asm volatile(
        "mma.sync.aligned.m16n8k8.row.col.f32.tf32.tf32.f32 "
        "{%0,%1,%2,%3}, {%4,%5,%6,%7}, {%8,%9}, {%0,%1,%2,%3};"
        : "+f"(acc[0]), "+f"(acc[1]), "+f"(acc[2]), "+f"(acc[3])
        : "r"(a[0]), "r"(a[1]), "r"(a[2]), "r"(a[3]), "r"(b[0]), "r"(b[1]));
}

// ---------------- tf32 tensor-core GEMM: C = epi(A @ W + bias) -------------
// A: (Mrows x K) row-major (if DUAL: A = cols [0,256), A2 = cols [256,K))
// W: (K x N) row-major, bias: (N), C row stride ldc.
// Block tile 128x64, BK=32, 256 threads (8 warps, 4x2), warp tile 32x32.
// EPI: 0 = identity, 1 = tanh, 2 = sigmoid
template<int EPI, bool DUAL>
__global__ __launch_bounds__(256)
void gemm_tf32(const float* __restrict__ A, const float* __restrict__ A2,
               const float* __restrict__ W, const float* __restrict__ bias,
               float* __restrict__ C, int N, int K, int ldc)
{
    const int BM = 128, BN = 64, BK = 32;
    __shared__ uint32_t As[BK][BM + 4];   // [k][m], tf32 bits
    __shared__ uint32_t Bs[BK][BN + 4];   // [k][n], tf32 bits

    const int bm   = blockIdx.y * BM;
    const int bn   = blockIdx.x * BN;
    const int tid  = threadIdx.x;
    const int lane = tid & 31;
    const int wid  = tid >> 5;
    const int wm   = (wid & 3) * 32;      // warp m-offset within block
    const int wn   = (wid >> 2) * 32;     // warp n-offset within block
    const int g    = lane >> 2;           // group id (0..7)
    const int q    = lane & 3;            // quad id  (0..3)

    float acc[2][4][4];                   // [m-tile][n-tile][frag]
    #pragma unroll
    for (int t = 0; t < 2; t++)
        #pragma unroll
        for (int j = 0; j < 4; j++)
            #pragma unroll
            for (int e = 0; e < 4; e++) acc[t][j][e] = 0.0f;

    for (int k0 = 0; k0 < K; k0 += BK) {
        // ---- load A tile (128 rows x 32 k), convert to tf32, transpose ----
        #pragma unroll
        for (int i = 0; i < 4; i++) {
            int idx = tid + i * 256;      // 1024 float4 slots
            int row = idx >> 3;
            int c4  = (idx & 7) * 4;
            int gk  = k0 + c4;
            float4 v;
            if (DUAL) {
                v = (gk < 256) ? *(const float4*)&A [(size_t)(bm + row) * 256 + gk]
                               : *(const float4*)&A2[(size_t)(bm + row) * 256 + gk - 256];
            } else {
                v = *(const float4*)&A[(size_t)(bm + row) * K + gk];
            }
            As[c4 + 0][row] = f2tf32(v.x);
            As[c4 + 1][row] = f2tf32(v.y);
            As[c4 + 2][row] = f2tf32(v.z);
            As[c4 + 3][row] = f2tf32(v.w);
        }
        // ---- load W tile (32 k x 64 n), convert to tf32 ----
        #pragma unroll
        for (int i = 0; i < 2; i++) {
            int idx = tid + i * 256;      // 512 float4 slots
            int row = idx >> 4;
            int c4  = (idx & 15) * 4;
            float4 v = *(const float4*)&W[(size_t)(k0 + row) * N + bn + c4];
            Bs[row][c4 + 0] = f2tf32(v.x);
            Bs[row][c4 + 1] = f2tf32(v.y);
            Bs[row][c4 + 2] = f2tf32(v.z);
            Bs[row][c4 + 3] = f2tf32(v.w);
        }
        __syncthreads();

        #pragma unroll
        for (int ks = 0; ks < BK; ks += 8) {
            uint32_t a[2][4];
            #pragma unroll
            for (int t = 0; t < 2; t++) {
                int r = wm + t * 16 + g;
                a[t][0] = As[ks + q    ][r];
                a[t][1] = As[ks + q    ][r + 8];
                a[t][2] = As[ks + q + 4][r];
                a[t][3] = As[ks + q + 4][r + 8];
            }
            uint32_t b[4][2];
            #pragma unroll
            for (int j = 0; j < 4; j++) {
                int c = wn + j * 8 + g;
                b[j][0] = Bs[ks + q    ][c];
                b[j][1] = Bs[ks + q + 4][c];
            }
            #pragma unroll
            for (int t = 0; t < 2; t++)
                #pragma unroll
                for (int j = 0; j < 4; j++)
                    mma_tf32(acc[t][j], a[t], b[j]);
        }
        __syncthreads();
    }

    // ---- epilogue: bias + activation, float2 stores ----
    #pragma unroll
    for (int t = 0; t < 2; t++) {
        #pragma unroll
        for (int j = 0; j < 4; j++) {
            int col = bn + wn + j * 8 + 2 * q;
            float b0 = bias[col], b1 = bias[col + 1];
            #pragma unroll
            for (int h = 0; h < 2; h++) {        // h=0 -> c0,c1 ; h=1 -> c2,c3
                int row = bm + wm + t * 16 + g + h * 8;
                float v0 = acc[t][j][2 * h]     + b0;
                float v1 = acc[t][j][2 * h + 1] + b1;
                if (EPI == 1) { v0 = tanhf(v0); v1 = tanhf(v1); }
                if (EPI == 2) { v0 = sigf(v0);  v1 = sigf(v1);  }
                *(float2*)&C[(size_t)row * ldc + col] = make_float2(v0, v1);
            }
        }
    }
}

// ---------------- GRU elementwise (keras reset_after=True) -----------------
__global__ void gru_kernel(const float* __restrict__ h_prev)
{
    int idx = blockIdx.x * blockDim.x + threadIdx.x;
    if (idx >= B_ * D_) return;
    int b = idx >> 8, d = idx & 255;
    const float* xp = g_xp + (size_t)b * 768;
    const float* hp = g_hp + (size_t)b * 768;
    float z  = sigf(xp[d]       + hp[d]);
    float r  = sigf(xp[256 + d] + hp[256 + d]);
    float hc = tanhf(xp[512 + d] + r * hp[512 + d]);
    float h  = h_prev[idx];
    g_gru[idx] = z * h + (1.0f - z) * hc;
}

// ---------------- attention: one warp per (b, h) ----------------------------
__global__ void attn_kernel()
{
    int gw   = (blockIdx.x * blockDim.x + threadIdx.x) >> 5;
    int lane = threadIdx.x & 31;
    if (gw >= B_ * H_) return;
    int b = gw >> 2;
    int h = gw & 3;

    const float* qp = g_q + (size_t)b * D_ + h * DK_;
    float q0 = qp[2 * lane], q1 = qp[2 * lane + 1];

    float sc[M_];
    #pragma unroll
    for (int m = 0; m < M_; m++) {
        const float* kp = g_k + ((size_t)b * M_ + m) * D_ + h * DK_;
        float p = q0 * kp[2 * lane] + q1 * kp[2 * lane + 1];
        #pragma unroll
        for (int o = 16; o > 0; o >>= 1) p += __shfl_xor_sync(0xffffffffu, p, o);
        sc[m] = p * 0.125f;
    }
    float mx = sc[0];
    #pragma unroll
    for (int m = 1; m < M_; m++) mx = fmaxf(mx, sc[m]);
    float sum = 0.0f;
    #pragma unroll
    for (int m = 0; m < M_; m++) { sc[m] = expf(sc[m] - mx); sum += sc[m]; }
    float inv = 1.0f / sum;

    float c0 = 0.0f, c1 = 0.0f;
    #pragma unroll
    for (int m = 0; m < M_; m++) {
        const float* vp = g_v + ((size_t)b * M_ + m) * D_ + h * DK_;
        float a = sc[m] * inv;
        c0 += a * vp[2 * lane];
        c1 += a * vp[2 * lane + 1];
    }
    float* cp = g_ctxh + (size_t)b * D_ + h * DK_;
    cp[2 * lane]     = c0;
    cp[2 * lane + 1] = c1;
}

// ---------------- LayerNorm (warp per row, D = 256) -------------------------
__device__ __forceinline__ void ln_row(const float* x8, int lane,
                                       const float* __restrict__ gm,
                                       const float* __restrict__ bt,
                                       float* __restrict__ yrow)
{
    float s = 0.0f, ss = 0.0f;
    #pragma unroll
    for (int i = 0; i < 8; i++) { s += x8[i]; ss += x8[i] * x8[i]; }
    #pragma unroll
    for (int o = 16; o > 0; o >>= 1) {
        s  += __shfl_xor_sync(0xffffffffu, s,  o);
        ss += __shfl_xor_sync(0xffffffffu, ss, o);
    }
    float mu  = s * (1.0f / 256.0f);
    float var = ss * (1.0f / 256.0f) - mu * mu;
    float inv = rsqrtf(var + 1e-3f);
    float out[8];
    #pragma unroll
    for (int i = 0; i < 8; i++) {
        int d = lane * 8 + i;
        out[i] = (x8[i] - mu) * inv * gm[d] + bt[d];
    }
    *(float4*)(yrow + lane * 8)     = make_float4(out[0], out[1], out[2], out[3]);
    *(float4*)(yrow + lane * 8 + 4) = make_float4(out[4], out[5], out[6], out[7]);
}

__global__ void ln_kernel(const float* __restrict__ x, const float* __restrict__ gm,
                          const float* __restrict__ bt, float* __restrict__ y)
{
    int w    = (blockIdx.x * blockDim.x + threadIdx.x) >> 5;
    int lane = threadIdx.x & 31;
    if (w >= B_) return;
    const float* row = x + (size_t)w * D_;
    float4 v0 = *(const float4*)(row + lane * 8);
    float4 v1 = *(const float4*)(row + lane * 8 + 4);
    float x8[8] = {v0.x, v0.y, v0.z, v0.w, v1.x, v1.y, v1.z, v1.w};
    ln_row(x8, lane, gm, bt, y + (size_t)w * D_);
}

__global__ void blend_ln_kernel(const float* __restrict__ gm,
                                const float* __restrict__ bt,
                                float* __restrict__ out)
{
    int w    = (blockIdx.x * blockDim.x + threadIdx.x) >> 5;
    int lane = threadIdx.x & 31;
    if (w >= B_) return;
    size_t base = (size_t)w * D_ + lane * 8;
    float x8[8];
    #pragma unroll
    for (int i = 0; i < 8; i++) {
        float a = g_alph[base + i];
        x8[i] = (1.0f - a) * g_gru[base + i] + a * g_ctxp[base + i];
    }
    ln_row(x8, lane, gm, bt, out + (size_t)w * D_);
}

// ---------------- memory shift: out_mem[b, 0:9D] = mem[b, D:10D] ------------
__global__ void memshift_kernel(const float* __restrict__ memflat,
                                float* __restrict__ outmem)
{
    const int per = (M_ - 1) * D_ / 4;   // 576 float4 per row
    int idx = blockIdx.x * blockDim.x + threadIdx.x;
    if (idx >= B_ * per) return;
    int b = idx / per, j = idx - b * per;
    const float4* src = (const float4*)(memflat + (size_t)b * (M_ * D_) + D_);
    float4*       dst = (float4*)(outmem + (size_t)b * (M_ * D_));
    dst[j] = src[j];
}

// ---------------- host ------------------------------------------------------
extern "C" void kernel_launch(void* const* d_in, const int* in_sizes, int n_in,
                              void* d_out, int out_size)
{
    const float* inputs    = (const float*)d_in[0];
    const float* h_prev    = (const float*)d_in[1];
    const float* memflat   = (const float*)d_in[2];
    const float* W_in      = (const float*)d_in[3];
    const float* b_in      = (const float*)d_in[4];
    const float* gru_k     = (const float*)d_in[5];
    const float* gru_rk    = (const float*)d_in[6];
    const float* gru_b     = (const float*)d_in[7];
    const float* Wq        = (const float*)d_in[8];
    const float* bq        = (const float*)d_in[9];
    const float* Wk        = (const float*)d_in[10];
    const float* bk        = (const float*)d_in[11];
    const float* Wv        = (const float*)d_in[12];
    const float* bv        = (const float*)d_in[13];
    const float* Wo        = (const float*)d_in[14];
    const float* bo        = (const float*)d_in[15];
    const float* g_attn    = (const float*)d_in[16];
    const float* beta_attn = (const float*)d_in[17];
    const float* g_out     = (const float*)d_in[18];
    const float* beta_out  = (const float*)d_in[19];
    const float* W_ctx     = (const float*)d_in[20];
    const float* b_ctx     = (const float*)d_in[21];
    const float* W_gate    = (const float*)d_in[22];
    const float* b_gate    = (const float*)d_in[23];
    const float* W_mem     = (const float*)d_in[24];
    const float* b_mem     = (const float*)d_in[25];
    float* out = (float*)d_out;

    float *zP, *xpP, *hpP, *gruP, *qP, *kP, *vP, *ctxhP, *ctxP, *ctxpP, *alphP;
    cudaGetSymbolAddress((void**)&zP,    g_z);
    cudaGetSymbolAddress((void**)&xpP,   g_xp);
    cudaGetSymbolAddress((void**)&hpP,   g_hp);
    cudaGetSymbolAddress((void**)&gruP,  g_gru);
    cudaGetSymbolAddress((void**)&qP,    g_q);
    cudaGetSymbolAddress((void**)&kP,    g_k);
    cudaGetSymbolAddress((void**)&vP,    g_v);
    cudaGetSymbolAddress((void**)&ctxhP, g_ctxh);
    cudaGetSymbolAddress((void**)&ctxP,  g_ctx);
    cudaGetSymbolAddress((void**)&ctxpP, g_ctxp);
    cudaGetSymbolAddress((void**)&alphP, g_alph);

    const dim3 blk(256);
    const dim3 gB (4, 64);     // 8192 x 256   (N=256 -> 4 blocks in x)
    const dim3 gB3(12, 64);    // 8192 x 768   (N=768 -> 12)
    const dim3 gGate(4, 64);   // 8192 x 256, K=512 (gate: N=256 -> 4!)
    const dim3 gKV(4, 640);    // 81920 x 256

    // K/V projections (independent, biggest) first
    gemm_tf32<0,false><<<gKV, blk>>>(memflat, nullptr, Wk, bk, kP, 256, 256, 256);
    gemm_tf32<0,false><<<gKV, blk>>>(memflat, nullptr, Wv, bv, vP, 256, 256, 256);

    // z_t, GRU
    gemm_tf32<0,false><<<gB,  blk>>>(inputs, nullptr, W_in,   b_in,        zP,  256, 256, 256);
    gemm_tf32<0,false><<<gB3, blk>>>(zP,     nullptr, gru_k,  gru_b,       xpP, 768, 256, 768);
    gemm_tf32<0,false><<<gB3, blk>>>(h_prev, nullptr, gru_rk, gru_b + 768, hpP, 768, 256, 768);
    gru_kernel<<<(B_ * D_ + 255) / 256, 256>>>(h_prev);

    // attention
    gemm_tf32<0,false><<<gB, blk>>>(gruP, nullptr, Wq, bq, qP, 256, 256, 256);
    attn_kernel<<<(B_ * H_ * 32 + 255) / 256, 256>>>();
    gemm_tf32<0,false><<<gB, blk>>>(ctxhP, nullptr, Wo, bo, ctxP, 256, 256, 256);
    ln_kernel<<<(B_ * 32 + 255) / 256, 256>>>(ctxP, g_attn, beta_attn, ctxP);

    // ctx_p, gate, blend+LN -> h_corr
    gemm_tf32<1,false><<<gB,    blk>>>(ctxP, nullptr, W_ctx,  b_ctx,  ctxpP, 256, 256, 256);
    gemm_tf32<2,true ><<<gGate, blk>>>(gruP, ctxpP,   W_gate, b_gate, alphP, 256, 512, 256);
    blend_ln_kernel<<<(B_ * 32 + 255) / 256, 256>>>(g_out, beta_out, out);

    // memory write: shifted copy + new entry in last slot
    memshift_kernel<<<(B_ * 576 + 255) / 256, 256>>>(memflat, out + B_ * D_);
    gemm_tf32<0,false><<<gB, blk>>>(zP, nullptr, W_mem, b_mem,
                                    out + B_ * D_ + (M_ - 1) * D_, 256, 256, M_ * D_);
}

// round 6
// speedup vs baseline: 1.3542x; 1.3531x over previous
#include <cuda_runtime.h>
#include <math.h>
#include <stdint.h>

#define B_  8192
#define D_  256
#define M_  10
#define H_  4
#define DK_ 64

// ---------------- scratch (device globals; no allocation allowed) ----------
__device__ float g_z   [B_*D_];
__device__ float g_xp  [B_*3*D_];
__device__ float g_hp  [B_*3*D_];
__device__ float g_gru [B_*D_];
__device__ float g_q   [B_*D_];
__device__ float g_k   [B_*M_*D_];
__device__ float g_v   [B_*M_*D_];
__device__ float g_ctxh[B_*D_];
__device__ float g_ctx [B_*D_];
__device__ float g_ctxp[B_*D_];
__device__ float g_alph[B_*D_];

__device__ __forceinline__ float sigf(float x) { return 1.0f / (1.0f + expf(-x)); }

__device__ __forceinline__ uint32_t f2tf32(float f) {
    uint32_t u;
    asm("cvt.rna.tf32.f32 %0, %1;" : "=r"(u) : "f"(f));
    return u;
}

__device__ __forceinline__ void mma_tf32(float acc[4], const uint32_t a[4],
                                         uint32_t b0, uint32_t b1) {
    asm volatile(
        "mma.sync.aligned.m16n8k8.row.col.f32.tf32.tf32.f32 "
        "{%0,%1,%2,%3}, {%4,%5,%6,%7}, {%8,%9}, {%0,%1,%2,%3};"
        : "+f"(acc[0]), "+f"(acc[1]), "+f"(acc[2]), "+f"(acc[3])
        : "r"(a[0]), "r"(a[1]), "r"(a[2]), "r"(a[3]), "r"(b0), "r"(b1));
}

// ---- smem geometry (words) ----
#define AS_STRIDE 36                     // words per A m-row (32 + 4 pad)
#define ABUF_W    (128 * AS_STRIDE)      // 4608 words
#define BBUF_W    (32 * 64)              // 2048 words (swizzled, no pad)
#define BOFF_W    (2 * ABUF_W)           // B region starts after 2 A buffers
#define SMEM_W    (2 * ABUF_W + 2 * BBUF_W)
#define SMEM_BYTES (SMEM_W * 4)          // 53248

// ---------------- tf32 tensor-core GEMM: C = epi(A @ W + bias) -------------
// Block tile 128x64, BK=32, 256 threads (8 warps, 4m x 2n), warp tile 32x32.
// A fragments via ldmatrix (b16 trick), B via swizzled LDS.128,
// double-buffered smem, 1 sync per K-tile.
// EPI: 0 = identity, 1 = tanh, 2 = sigmoid
template<int EPI, bool DUAL>
__global__ __launch_bounds__(256, 2)
void gemm_tf32(const float* __restrict__ A, const float* __restrict__ A2,
               const float* __restrict__ W, const float* __restrict__ bias,
               float* __restrict__ C, int N, int K, int ldc)
{
    extern __shared__ uint32_t sm[];
    const uint32_t sbase = (uint32_t)__cvta_generic_to_shared(sm);

    const int bm   = blockIdx.y * 128;
    const int bn   = blockIdx.x * 64;
    const int tid  = threadIdx.x;
    const int lane = tid & 31;
    const int wid  = tid >> 5;
    const int wm   = (wid & 3) * 32;
    const int wn   = (wid >> 2) * 32;
    const int g    = lane >> 2;
    const int q    = lane & 3;

    // ldmatrix per-lane address offsets (bytes within an A buffer)
    const int mi = lane >> 3, rr = lane & 7;
    const uint32_t a_off0 = ((wm + (mi & 1) * 8 + rr) * AS_STRIDE + (mi >> 1) * 4) * 4;
    const uint32_t a_off1 = a_off0 + 16 * AS_STRIDE * 4;

    // B fragment chunk (swizzled) per lane (bytes within a B buffer)
    const int w4 = wn >> 5;                  // 0 or 1
    const int gb = (g >> 2) & 1;
    const int chunkp = (2 * g + (w4 ^ gb)) ^ (q << 2);
    const uint32_t b_off = (q * 64 + chunkp * 4) * 4;   // row k=q, chunk

    float acc[2][4][4];
    #pragma unroll
    for (int t = 0; t < 2; t++)
        #pragma unroll
        for (int j = 0; j < 4; j++)
            #pragma unroll
            for (int e = 0; e < 4; e++) acc[t][j][e] = 0.0f;

    // per-thread gmem tile indices
    // A: 4 float4/thread: row = idx>>3, c4 = (idx&7)*4
    // B: 2 float4/thread: kk  = idx>>4, n0 = (idx&15)*4
    float4 av[4], bv[2];

    auto load_tiles = [&](int k0) {
        #pragma unroll
        for (int i = 0; i < 4; i++) {
            int idx = tid + i * 256;
            int row = idx >> 3, c4 = (idx & 7) * 4;
            int gk  = k0 + c4;
            if (DUAL) {
                av[i] = (gk < 256) ? *(const float4*)&A [(size_t)(bm + row) * 256 + gk]
                                   : *(const float4*)&A2[(size_t)(bm + row) * 256 + gk - 256];
            } else {
                av[i] = *(const float4*)&A[(size_t)(bm + row) * K + gk];
            }
        }
        #pragma unroll
        for (int i = 0; i < 2; i++) {
            int idx = tid + i * 256;
            int kk = idx >> 4, n0 = (idx & 15) * 4;
            bv[i] = *(const float4*)&W[(size_t)(k0 + kk) * N + bn + n0];
        }
    };

    auto store_tiles = [&](int buf) {
        uint32_t* as = sm + buf * ABUF_W;
        uint32_t* bs = sm + BOFF_W + buf * BBUF_W;
        #pragma unroll
        for (int i = 0; i < 4; i++) {
            int idx = tid + i * 256;
            int row = idx >> 3, c4 = (idx & 7) * 4;
            uint4 w = make_uint4(f2tf32(av[i].x), f2tf32(av[i].y),
                                 f2tf32(av[i].z), f2tf32(av[i].w));
            *(uint4*)&as[row * AS_STRIDE + c4] = w;
        }
        #pragma unroll
        for (int i = 0; i < 2; i++) {
            int idx = tid + i * 256;
            int kk = idx >> 4, n0 = (idx & 15) * 4;
            float vals[4] = {bv[i].x, bv[i].y, bv[i].z, bv[i].w};
            #pragma unroll
            for (int e = 0; e < 4; e++) {
                int n   = n0 + e;
                int npr = ((n & 7) << 3) + ((n >> 3) ^ (n & 4));
                int wrd = kk * 64 + (((npr >> 2) ^ ((kk & 3) << 2)) << 2) + (npr & 3);
                bs[wrd] = f2tf32(vals[e]);
            }
        }
    };

    auto compute = [&](int buf) {
        const uint32_t asb = sbase + buf * (ABUF_W * 4);
        const uint32_t bsb = sbase + (BOFF_W + buf * BBUF_W) * 4;
        #pragma unroll
        for (int kb = 0; kb < 4; kb++) {
            uint32_t a0[4], a1[4];
            uint32_t aaddr0 = asb + a_off0 + kb * 32;
            uint32_t aaddr1 = asb + a_off1 + kb * 32;
            asm volatile("ldmatrix.sync.aligned.m8n8.x4.shared.b16 {%0,%1,%2,%3}, [%4];"
                : "=r"(a0[0]), "=r"(a0[1]), "=r"(a0[2]), "=r"(a0[3]) : "r"(aaddr0));
            asm volatile("ldmatrix.sync.aligned.m8n8.x4.shared.b16 {%0,%1,%2,%3}, [%4];"
                : "=r"(a1[0]), "=r"(a1[1]), "=r"(a1[2]), "=r"(a1[3]) : "r"(aaddr1));
            uint32_t bq0[4], bq1[4];
            uint32_t baddr0 = bsb + b_off + kb * 2048;         // qh=0 rows
            uint32_t baddr1 = baddr0 + 1024;                   // qh=1 rows (+4 k-rows)
            asm volatile("ld.shared.v4.b32 {%0,%1,%2,%3}, [%4];"
                : "=r"(bq0[0]), "=r"(bq0[1]), "=r"(bq0[2]), "=r"(bq0[3]) : "r"(baddr0));
            asm volatile("ld.shared.v4.b32 {%0,%1,%2,%3}, [%4];"
                : "=r"(bq1[0]), "=r"(bq1[1]), "=r"(bq1[2]), "=r"(bq1[3]) : "r"(baddr1));
            #pragma unroll
            for (int j = 0; j < 4; j++) {
                mma_tf32(acc[0][j], a0, bq0[j], bq1[j]);
                mma_tf32(acc[1][j], a1, bq0[j], bq1[j]);
            }
        }
    };

    const int NIT = K >> 5;
    load_tiles(0);
    store_tiles(0);
    __syncthreads();

    for (int it = 0; it < NIT; it++) {
        int buf = it & 1;
        if (it + 1 < NIT) load_tiles((it + 1) * 32);
        compute(buf);
        if (it + 1 < NIT) {
            store_tiles(buf ^ 1);
            __syncthreads();
        }
    }

    // ---- epilogue: bias + activation, float2 stores ----
    #pragma unroll
    for (int t = 0; t < 2; t++) {
        #pragma unroll
        for (int j = 0; j < 4; j++) {
            int col = bn + wn + j * 8 + 2 * q;
            float b0 = bias[col], b1 = bias[col + 1];
            #pragma unroll
            for (int h = 0; h < 2; h++) {
                int row = bm + wm + t * 16 + g + h * 8;
                float v0 = acc[t][j][2 * h]     + b0;
                float v1 = acc[t][j][2 * h + 1] + b1;
                if (EPI == 1) { v0 = tanhf(v0); v1 = tanhf(v1); }
                if (EPI == 2) { v0 = sigf(v0);  v1 = sigf(v1);  }
                *(float2*)&C[(size_t)row * ldc + col] = make_float2(v0, v1);
            }
        }
    }
}

// ---------------- GRU elementwise (keras reset_after=True) -----------------
__global__ void gru_kernel(const float* __restrict__ h_prev)
{
    int idx = blockIdx.x * blockDim.x + threadIdx.x;
    if (idx >= B_ * D_) return;
    int b = idx >> 8, d = idx & 255;
    const float* xp = g_xp + (size_t)b * 768;
    const float* hp = g_hp + (size_t)b * 768;
    float z  = sigf(xp[d]       + hp[d]);
    float r  = sigf(xp[256 + d] + hp[256 + d]);
    float hc = tanhf(xp[512 + d] + r * hp[512 + d]);
    float h  = h_prev[idx];
    g_gru[idx] = z * h + (1.0f - z) * hc;
}

// ---------------- attention: one warp per (b, h) ----------------------------
__global__ void attn_kernel()
{
    int gw   = (blockIdx.x * blockDim.x + threadIdx.x) >> 5;
    int lane = threadIdx.x & 31;
    if (gw >= B_ * H_) return;
    int b = gw >> 2;
    int h = gw & 3;

    const float* qp = g_q + (size_t)b * D_ + h * DK_;
    float q0 = qp[2 * lane], q1 = qp[2 * lane + 1];

    float sc[M_];
    #pragma unroll
    for (int m = 0; m < M_; m++) {
        const float* kp = g_k + ((size_t)b * M_ + m) * D_ + h * DK_;
        float p = q0 * kp[2 * lane] + q1 * kp[2 * lane + 1];
        #pragma unroll
        for (int o = 16; o > 0; o >>= 1) p += __shfl_xor_sync(0xffffffffu, p, o);
        sc[m] = p * 0.125f;
    }
    float mx = sc[0];
    #pragma unroll
    for (int m = 1; m < M_; m++) mx = fmaxf(mx, sc[m]);
    float sum = 0.0f;
    #pragma unroll
    for (int m = 0; m < M_; m++) { sc[m] = expf(sc[m] - mx); sum += sc[m]; }
    float inv = 1.0f / sum;

    float c0 = 0.0f, c1 = 0.0f;
    #pragma unroll
    for (int m = 0; m < M_; m++) {
        const float* vp = g_v + ((size_t)b * M_ + m) * D_ + h * DK_;
        float a = sc[m] * inv;
        c0 += a * vp[2 * lane];
        c1 += a * vp[2 * lane + 1];
    }
    float* cp = g_ctxh + (size_t)b * D_ + h * DK_;
    cp[2 * lane]     = c0;
    cp[2 * lane + 1] = c1;
}

// ---------------- LayerNorm (warp per row, D = 256) -------------------------
__device__ __forceinline__ void ln_row(const float* x8, int lane,
                                       const float* __restrict__ gm,
                                       const float* __restrict__ bt,
                                       float* __restrict__ yrow)
{
    float s = 0.0f, ss = 0.0f;
    #pragma unroll
    for (int i = 0; i < 8; i++) { s += x8[i]; ss += x8[i] * x8[i]; }
    #pragma unroll
    for (int o = 16; o > 0; o >>= 1) {
        s  += __shfl_xor_sync(0xffffffffu, s,  o);
        ss += __shfl_xor_sync(0xffffffffu, ss, o);
    }
    float mu  = s * (1.0f / 256.0f);
    float var = ss * (1.0f / 256.0f) - mu * mu;
    float inv = rsqrtf(var + 1e-3f);
    float out[8];
    #pragma unroll
    for (int i = 0; i < 8; i++) {
        int d = lane * 8 + i;
        out[i] = (x8[i] - mu) * inv * gm[d] + bt[d];
    }
    *(float4*)(yrow + lane * 8)     = make_float4(out[0], out[1], out[2], out[3]);
    *(float4*)(yrow + lane * 8 + 4) = make_float4(out[4], out[5], out[6], out[7]);
}

__global__ void ln_kernel(const float* __restrict__ x, const float* __restrict__ gm,
                          const float* __restrict__ bt, float* __restrict__ y)
{
    int w    = (blockIdx.x * blockDim.x + threadIdx.x) >> 5;
    int lane = threadIdx.x & 31;
    if (w >= B_) return;
    const float* row = x + (size_t)w * D_;
    float4 v0 = *(const float4*)(row + lane * 8);
    float4 v1 = *(const float4*)(row + lane * 8 + 4);
    float x8[8] = {v0.x, v0.y, v0.z, v0.w, v1.x, v1.y, v1.z, v1.w};
    ln_row(x8, lane, gm, bt, y + (size_t)w * D_);
}

__global__ void blend_ln_kernel(const float* __restrict__ gm,
                                const float* __restrict__ bt,
                                float* __restrict__ out)
{
    int w    = (blockIdx.x * blockDim.x + threadIdx.x) >> 5;
    int lane = threadIdx.x & 31;
    if (w >= B_) return;
    size_t base = (size_t)w * D_ + lane * 8;
    float x8[8];
    #pragma unroll
    for (int i = 0; i < 8; i++) {
        float a = g_alph[base + i];
        x8[i] = (1.0f - a) * g_gru[base + i] + a * g_ctxp[base + i];
    }
    ln_row(x8, lane, gm, bt, out + (size_t)w * D_);
}

// ---------------- memory shift: out_mem[b, 0:9D] = mem[b, D:10D] ------------
__global__ void memshift_kernel(const float* __restrict__ memflat,
                                float* __restrict__ outmem)
{
    const int per = (M_ - 1) * D_ / 4;
    int idx = blockIdx.x * blockDim.x + threadIdx.x;
    if (idx >= B_ * per) return;
    int b = idx / per, j = idx - b * per;
    const float4* src = (const float4*)(memflat + (size_t)b * (M_ * D_) + D_);
    float4*       dst = (float4*)(outmem + (size_t)b * (M_ * D_));
    dst[j] = src[j];
}

// ---------------- host ------------------------------------------------------
extern "C" void kernel_launch(void* const* d_in, const int* in_sizes, int n_in,
                              void* d_out, int out_size)
{
    const float* inputs    = (const float*)d_in[0];
    const float* h_prev    = (const float*)d_in[1];
    const float* memflat   = (const float*)d_in[2];
    const float* W_in      = (const float*)d_in[3];
    const float* b_in      = (const float*)d_in[4];
    const float* gru_k     = (const float*)d_in[5];
    const float* gru_rk    = (const float*)d_in[6];
    const float* gru_b     = (const float*)d_in[7];
    const float* Wq        = (const float*)d_in[8];
    const float* bq        = (const float*)d_in[9];
    const float* Wk        = (const float*)d_in[10];
    const float* bk        = (const float*)d_in[11];
    const float* Wv        = (const float*)d_in[12];
    const float* bv        = (const float*)d_in[13];
    const float* Wo        = (const float*)d_in[14];
    const float* bo        = (const float*)d_in[15];
    const float* g_attn    = (const float*)d_in[16];
    const float* beta_attn = (const float*)d_in[17];
    const float* g_out     = (const float*)d_in[18];
    const float* beta_out  = (const float*)d_in[19];
    const float* W_ctx     = (const float*)d_in[20];
    const float* b_ctx     = (const float*)d_in[21];
    const float* W_gate    = (const float*)d_in[22];
    const float* b_gate    = (const float*)d_in[23];
    const float* W_mem     = (const float*)d_in[24];
    const float* b_mem     = (const float*)d_in[25];
    float* out = (float*)d_out;

    float *zP, *xpP, *hpP, *gruP, *qP, *kP, *vP, *ctxhP, *ctxP, *ctxpP, *alphP;
    cudaGetSymbolAddress((void**)&zP,    g_z);
    cudaGetSymbolAddress((void**)&xpP,   g_xp);
    cudaGetSymbolAddress((void**)&hpP,   g_hp);
    cudaGetSymbolAddress((void**)&gruP,  g_gru);
    cudaGetSymbolAddress((void**)&qP,    g_q);
    cudaGetSymbolAddress((void**)&kP,    g_k);
    cudaGetSymbolAddress((void**)&vP,    g_v);
    cudaGetSymbolAddress((void**)&ctxhP, g_ctxh);
    cudaGetSymbolAddress((void**)&ctxP,  g_ctx);
    cudaGetSymbolAddress((void**)&ctxpP, g_ctxp);
    cudaGetSymbolAddress((void**)&alphP, g_alph);

    // opt-in to >48KB dynamic smem for each instantiation (idempotent)
    cudaFuncSetAttribute(gemm_tf32<0,false>, cudaFuncAttributeMaxDynamicSharedMemorySize, SMEM_BYTES);
    cudaFuncSetAttribute(gemm_tf32<1,false>, cudaFuncAttributeMaxDynamicSharedMemorySize, SMEM_BYTES);
    cudaFuncSetAttribute(gemm_tf32<2,true >, cudaFuncAttributeMaxDynamicSharedMemorySize, SMEM_BYTES);

    const dim3 blk(256);
    const dim3 gB (4, 64);     // 8192 x 256
    const dim3 gB3(12, 64);    // 8192 x 768
    const dim3 gGate(4, 64);   // 8192 x 256, K=512
    const dim3 gKV(4, 640);    // 81920 x 256

    gemm_tf32<0,false><<<gKV, blk, SMEM_BYTES>>>(memflat, nullptr, Wk, bk, kP, 256, 256, 256);
    gemm_tf32<0,false><<<gKV, blk, SMEM_BYTES>>>(memflat, nullptr, Wv, bv, vP, 256, 256, 256);

    gemm_tf32<0,false><<<gB,  blk, SMEM_BYTES>>>(inputs, nullptr, W_in,   b_in,        zP,  256, 256, 256);
    gemm_tf32<0,false><<<gB3, blk, SMEM_BYTES>>>(zP,     nullptr, gru_k,  gru_b,       xpP, 768, 256, 768);
    gemm_tf32<0,false><<<gB3, blk, SMEM_BYTES>>>(h_prev, nullptr, gru_rk, gru_b + 768, hpP, 768, 256, 768);
    gru_kernel<<<(B_ * D_ + 255) / 256, 256>>>(h_prev);

    gemm_tf32<0,false><<<gB, blk, SMEM_BYTES>>>(gruP, nullptr, Wq, bq, qP, 256, 256, 256);
    attn_kernel<<<(B_ * H_ * 32 + 255) / 256, 256>>>();
    gemm_tf32<0,false><<<gB, blk, SMEM_BYTES>>>(ctxhP, nullptr, Wo, bo, ctxP, 256, 256, 256);
    ln_kernel<<<(B_ * 32 + 255) / 256, 256>>>(ctxP, g_attn, beta_attn, ctxP);

    gemm_tf32<1,false><<<gB,    blk, SMEM_BYTES>>>(ctxP, nullptr, W_ctx,  b_ctx,  ctxpP, 256, 256, 256);
    gemm_tf32<2,true ><<<gGate, blk, SMEM_BYTES>>>(gruP, ctxpP,   W_gate, b_gate, alphP, 256, 512, 256);
    blend_ln_kernel<<<(B_ * 32 + 255) / 256, 256>>>(g_out, beta_out, out);

    memshift_kernel<<<(B_ * 576 + 255) / 256, 256>>>(memflat, out + B_ * D_);
    gemm_tf32<0,false><<<gB, blk, SMEM_BYTES>>>(zP, nullptr, W_mem, b_mem,
                                                out + B_ * D_ + (M_ - 1) * D_, 256, 256, M_ * D_);
}

// round 7
// speedup vs baseline: 1.5604x; 1.1523x over previous
#include <cuda_runtime.h>
#include <math.h>
#include <stdint.h>

#define B_  8192
#define D_  256
#define M_  10
#define H_  4
#define DK_ 64

// ---------------- scratch (device globals; no allocation allowed) ----------
__device__ float g_z   [B_*D_];
__device__ float g_xp  [B_*3*D_];
__device__ float g_hp  [B_*3*D_];
__device__ float g_gru [B_*D_];
__device__ float g_q   [B_*D_];
__device__ float g_k   [B_*M_*D_];
__device__ float g_v   [B_*M_*D_];
__device__ float g_ctxh[B_*D_];
__device__ float g_ctx [B_*D_];
__device__ float g_ctxp[B_*D_];
__device__ float g_alph[B_*D_];

__device__ __forceinline__ float sigf(float x) { return 1.0f / (1.0f + expf(-x)); }

__device__ __forceinline__ void mma_tf32(float acc[4], const uint32_t a[4],
                                         uint32_t b0, uint32_t b1) {
    asm volatile(
        "mma.sync.aligned.m16n8k8.row.col.f32.tf32.tf32.f32 "
        "{%0,%1,%2,%3}, {%4,%5,%6,%7}, {%8,%9}, {%0,%1,%2,%3};"
        : "+f"(acc[0]), "+f"(acc[1]), "+f"(acc[2]), "+f"(acc[3])
        : "r"(a[0]), "r"(a[1]), "r"(a[2]), "r"(a[3]), "r"(b0), "r"(b1));
}

__device__ __forceinline__ void cp16(uint32_t dst, const void* src) {
    asm volatile("cp.async.cg.shared.global [%0], [%1], 16;" :: "r"(dst), "l"(src));
}
__device__ __forceinline__ void cp_commit() {
    asm volatile("cp.async.commit_group;" ::: "memory");
}
template<int N>
__device__ __forceinline__ void cp_wait() {
    asm volatile("cp.async.wait_group %0;" :: "n"(N) : "memory");
}

// ---- smem geometry (words) ----
#define AS_STRIDE 36                       // words per A m-row (32 + 4 pad)
#define ABUF_W    (128 * AS_STRIDE)        // 4608 words
#define BS_STRIDE 72                       // words per B k-row (64 + 8 pad)
#define BBUF_W    (32 * BS_STRIDE)         // 2304 words
#define STAGE_W   (ABUF_W + BBUF_W)        // 6912 words
#define STAGES    4
#define SMEM_BYTES (STAGES * STAGE_W * 4)  // 110592

// ---------------- tf32 tensor-core GEMM: C = epi(A @ W + bias) -------------
// Block tile 128x64, BK=32, 256 threads (8 warps, 4m x 2n), warp tile 32x32.
// cp.async gmem->smem (raw f32 bits; HMMA truncates to tf32), 4-stage pipe,
// A frags via ldmatrix (b16 trick), B frags via conflict-free scalar LDS.
// EPI: 0 = identity, 1 = tanh, 2 = sigmoid
template<int EPI, bool DUAL>
__global__ __launch_bounds__(256, 2)
void gemm_tf32(const float* __restrict__ A, const float* __restrict__ A2,
               const float* __restrict__ W, const float* __restrict__ bias,
               float* __restrict__ C, int N, int K, int ldc)
{
    extern __shared__ uint32_t sm[];
    const uint32_t sbase = (uint32_t)__cvta_generic_to_shared(sm);

    const int bm   = blockIdx.y * 128;
    const int bn   = blockIdx.x * 64;
    const int tid  = threadIdx.x;
    const int lane = tid & 31;
    const int wid  = tid >> 5;
    const int wm   = (wid & 3) * 32;
    const int wn   = (wid >> 2) * 32;
    const int g    = lane >> 2;
    const int q    = lane & 3;

    // ldmatrix per-lane address offsets (bytes within an A buffer)
    const int mi = lane >> 3, rr = lane & 7;
    const uint32_t a_off0 = ((wm + (mi & 1) * 8 + rr) * AS_STRIDE + (mi >> 1) * 4) * 4;
    const uint32_t a_off1 = a_off0 + 16 * AS_STRIDE * 4;

    // B fragment base offset (bytes within a B buffer): k-row q, col wn+g
    const uint32_t b_off = (q * BS_STRIDE + wn + g) * 4;

    float acc[2][4][4];
    #pragma unroll
    for (int t = 0; t < 2; t++)
        #pragma unroll
        for (int j = 0; j < 4; j++)
            #pragma unroll
            for (int e = 0; e < 4; e++) acc[t][j][e] = 0.0f;

    // ---- async tile fetch: gmem -> smem stage ----
    auto cp_tile = [&](int k0, int stage) {
        uint32_t abase = sbase + stage * (STAGE_W * 4);
        uint32_t bbase = abase + ABUF_W * 4;
        #pragma unroll
        for (int i = 0; i < 4; i++) {
            int idx = tid + i * 256;
            int row = idx >> 3, c4 = (idx & 7) * 4;
            int gk  = k0 + c4;
            const float* src;
            if (DUAL) {
                src = (gk < 256) ? &A [(size_t)(bm + row) * 256 + gk]
                                 : &A2[(size_t)(bm + row) * 256 + gk - 256];
            } else {
                src = &A[(size_t)(bm + row) * K + gk];
            }
            cp16(abase + (row * AS_STRIDE + c4) * 4, src);
        }
        #pragma unroll
        for (int i = 0; i < 2; i++) {
            int idx = tid + i * 256;
            int kk = idx >> 4, n0 = (idx & 15) * 4;
            cp16(bbase + (kk * BS_STRIDE + n0) * 4, &W[(size_t)(k0 + kk) * N + bn + n0]);
        }
    };

    // ---- fragment load for one k8 step ----
    auto load_frag = [&](uint32_t asb, uint32_t bsb, int kb,
                         uint32_t a0[4], uint32_t a1[4], uint32_t b0[4], uint32_t b1[4]) {
        uint32_t aaddr0 = asb + a_off0 + kb * 32;
        uint32_t aaddr1 = asb + a_off1 + kb * 32;
        asm volatile("ldmatrix.sync.aligned.m8n8.x4.shared.b16 {%0,%1,%2,%3}, [%4];"
            : "=r"(a0[0]), "=r"(a0[1]), "=r"(a0[2]), "=r"(a0[3]) : "r"(aaddr0));
        asm volatile("ldmatrix.sync.aligned.m8n8.x4.shared.b16 {%0,%1,%2,%3}, [%4];"
            : "=r"(a1[0]), "=r"(a1[1]), "=r"(a1[2]), "=r"(a1[3]) : "r"(aaddr1));
        uint32_t bb = bsb + b_off + kb * (8 * BS_STRIDE * 4);
        #pragma unroll
        for (int j = 0; j < 4; j++) {
            asm volatile("ld.shared.b32 %0, [%1];" : "=r"(b0[j]) : "r"(bb + j * 32));
            asm volatile("ld.shared.b32 %0, [%1];" : "=r"(b1[j]) : "r"(bb + j * 32 + 4 * BS_STRIDE * 4));
        }
    };

    auto compute = [&](int stage) {
        const uint32_t asb = sbase + stage * (STAGE_W * 4);
        const uint32_t bsb = asb + ABUF_W * 4;
        uint32_t a0[2][4], a1[2][4], b0[2][4], b1[2][4];
        load_frag(asb, bsb, 0, a0[0], a1[0], b0[0], b1[0]);
        #pragma unroll
        for (int kb = 0; kb < 4; kb++) {
            int cur = kb & 1, nxt = cur ^ 1;
            if (kb < 3) load_frag(asb, bsb, kb + 1, a0[nxt], a1[nxt], b0[nxt], b1[nxt]);
            #pragma unroll
            for (int j = 0; j < 4; j++) {
                mma_tf32(acc[0][j], a0[cur], b0[cur][j], b1[cur][j]);
                mma_tf32(acc[1][j], a1[cur], b0[cur][j], b1[cur][j]);
            }
        }
    };

    const int NIT = K >> 5;

    // prologue: fill STAGES-1 stages
    #pragma unroll
    for (int s = 0; s < STAGES - 1; s++) {
        if (s < NIT) cp_tile(s * 32, s);
        cp_commit();
    }

    for (int it = 0; it < NIT; it++) {
        cp_wait<STAGES - 2>();
        __syncthreads();
        int nt = it + STAGES - 1;
        if (nt < NIT) { cp_tile(nt * 32, nt & (STAGES - 1)); }
        cp_commit();
        compute(it & (STAGES - 1));
    }

    // ---- epilogue: bias + activation, float2 stores ----
    #pragma unroll
    for (int t = 0; t < 2; t++) {
        #pragma unroll
        for (int j = 0; j < 4; j++) {
            int col = bn + wn + j * 8 + 2 * q;
            float b0 = bias[col], b1 = bias[col + 1];
            #pragma unroll
            for (int h = 0; h < 2; h++) {
                int row = bm + wm + t * 16 + g + h * 8;
                float v0 = acc[t][j][2 * h]     + b0;
                float v1 = acc[t][j][2 * h + 1] + b1;
                if (EPI == 1) { v0 = tanhf(v0); v1 = tanhf(v1); }
                if (EPI == 2) { v0 = sigf(v0);  v1 = sigf(v1);  }
                *(float2*)&C[(size_t)row * ldc + col] = make_float2(v0, v1);
            }
        }
    }
}

// ---------------- GRU elementwise (keras reset_after=True) -----------------
__global__ void gru_kernel(const float* __restrict__ h_prev)
{
    int idx = blockIdx.x * blockDim.x + threadIdx.x;
    if (idx >= B_ * D_) return;
    int b = idx >> 8, d = idx & 255;
    const float* xp = g_xp + (size_t)b * 768;
    const float* hp = g_hp + (size_t)b * 768;
    float z  = sigf(xp[d]       + hp[d]);
    float r  = sigf(xp[256 + d] + hp[256 + d]);
    float hc = tanhf(xp[512 + d] + r * hp[512 + d]);
    float h  = h_prev[idx];
    g_gru[idx] = z * h + (1.0f - z) * hc;
}

// ---------------- attention: one warp per (b, h) ----------------------------
__global__ void attn_kernel()
{
    int gw   = (blockIdx.x * blockDim.x + threadIdx.x) >> 5;
    int lane = threadIdx.x & 31;
    if (gw >= B_ * H_) return;
    int b = gw >> 2;
    int h = gw & 3;

    const float* qp = g_q + (size_t)b * D_ + h * DK_;
    float q0 = qp[2 * lane], q1 = qp[2 * lane + 1];

    float sc[M_];
    #pragma unroll
    for (int m = 0; m < M_; m++) {
        const float* kp = g_k + ((size_t)b * M_ + m) * D_ + h * DK_;
        float p = q0 * kp[2 * lane] + q1 * kp[2 * lane + 1];
        #pragma unroll
        for (int o = 16; o > 0; o >>= 1) p += __shfl_xor_sync(0xffffffffu, p, o);
        sc[m] = p * 0.125f;
    }
    float mx = sc[0];
    #pragma unroll
    for (int m = 1; m < M_; m++) mx = fmaxf(mx, sc[m]);
    float sum = 0.0f;
    #pragma unroll
    for (int m = 0; m < M_; m++) { sc[m] = expf(sc[m] - mx); sum += sc[m]; }
    float inv = 1.0f / sum;

    float c0 = 0.0f, c1 = 0.0f;
    #pragma unroll
    for (int m = 0; m < M_; m++) {
        const float* vp = g_v + ((size_t)b * M_ + m) * D_ + h * DK_;
        float a = sc[m] * inv;
        c0 += a * vp[2 * lane];
        c1 += a * vp[2 * lane + 1];
    }
    float* cp = g_ctxh + (size_t)b * D_ + h * DK_;
    cp[2 * lane]     = c0;
    cp[2 * lane + 1] = c1;
}

// ---------------- LayerNorm (warp per row, D = 256) -------------------------
__device__ __forceinline__ void ln_row(const float* x8, int lane,
                                       const float* __restrict__ gm,
                                       const float* __restrict__ bt,
                                       float* __restrict__ yrow)
{
    float s = 0.0f, ss = 0.0f;
    #pragma unroll
    for (int i = 0; i < 8; i++) { s += x8[i]; ss += x8[i] * x8[i]; }
    #pragma unroll
    for (int o = 16; o > 0; o >>= 1) {
        s  += __shfl_xor_sync(0xffffffffu, s,  o);
        ss += __shfl_xor_sync(0xffffffffu, ss, o);
    }
    float mu  = s * (1.0f / 256.0f);
    float var = ss * (1.0f / 256.0f) - mu * mu;
    float inv = rsqrtf(var + 1e-3f);
    float out[8];
    #pragma unroll
    for (int i = 0; i < 8; i++) {
        int d = lane * 8 + i;
        out[i] = (x8[i] - mu) * inv * gm[d] + bt[d];
    }
    *(float4*)(yrow + lane * 8)     = make_float4(out[0], out[1], out[2], out[3]);
    *(float4*)(yrow + lane * 8 + 4) = make_float4(out[4], out[5], out[6], out[7]);
}

__global__ void ln_kernel(const float* __restrict__ x, const float* __restrict__ gm,
                          const float* __restrict__ bt, float* __restrict__ y)
{
    int w    = (blockIdx.x * blockDim.x + threadIdx.x) >> 5;
    int lane = threadIdx.x & 31;
    if (w >= B_) return;
    const float* row = x + (size_t)w * D_;
    float4 v0 = *(const float4*)(row + lane * 8);
    float4 v1 = *(const float4*)(row + lane * 8 + 4);
    float x8[8] = {v0.x, v0.y, v0.z, v0.w, v1.x, v1.y, v1.z, v1.w};
    ln_row(x8, lane, gm, bt, y + (size_t)w * D_);
}

__global__ void blend_ln_kernel(const float* __restrict__ gm,
                                const float* __restrict__ bt,
                                float* __restrict__ out)
{
    int w    = (blockIdx.x * blockDim.x + threadIdx.x) >> 5;
    int lane = threadIdx.x & 31;
    if (w >= B_) return;
    size_t base = (size_t)w * D_ + lane * 8;
    float x8[8];
    #pragma unroll
    for (int i = 0; i < 8; i++) {
        float a = g_alph[base + i];
        x8[i] = (1.0f - a) * g_gru[base + i] + a * g_ctxp[base + i];
    }
    ln_row(x8, lane, gm, bt, out + (size_t)w * D_);
}

// ---------------- memory shift: out_mem[b, 0:9D] = mem[b, D:10D] ------------
__global__ void memshift_kernel(const float* __restrict__ memflat,
                                float* __restrict__ outmem)
{
    const int per = (M_ - 1) * D_ / 4;
    int idx = blockIdx.x * blockDim.x + threadIdx.x;
    if (idx >= B_ * per) return;
    int b = idx / per, j = idx - b * per;
    const float4* src = (const float4*)(memflat + (size_t)b * (M_ * D_) + D_);
    float4*       dst = (float4*)(outmem + (size_t)b * (M_ * D_));
    dst[j] = src[j];
}

// ---------------- host ------------------------------------------------------
extern "C" void kernel_launch(void* const* d_in, const int* in_sizes, int n_in,
                              void* d_out, int out_size)
{
    const float* inputs    = (const float*)d_in[0];
    const float* h_prev    = (const float*)d_in[1];
    const float* memflat   = (const float*)d_in[2];
    const float* W_in      = (const float*)d_in[3];
    const float* b_in      = (const float*)d_in[4];
    const float* gru_k     = (const float*)d_in[5];
    const float* gru_rk    = (const float*)d_in[6];
    const float* gru_b     = (const float*)d_in[7];
    const float* Wq        = (const float*)d_in[8];
    const float* bq        = (const float*)d_in[9];
    const float* Wk        = (const float*)d_in[10];
    const float* bk        = (const float*)d_in[11];
    const float* Wv        = (const float*)d_in[12];
    const float* bv        = (const float*)d_in[13];
    const float* Wo        = (const float*)d_in[14];
    const float* bo        = (const float*)d_in[15];
    const float* g_attn    = (const float*)d_in[16];
    const float* beta_attn = (const float*)d_in[17];
    const float* g_out     = (const float*)d_in[18];
    const float* beta_out  = (const float*)d_in[19];
    const float* W_ctx     = (const float*)d_in[20];
    const float* b_ctx     = (const float*)d_in[21];
    const float* W_gate    = (const float*)d_in[22];
    const float* b_gate    = (const float*)d_in[23];
    const float* W_mem     = (const float*)d_in[24];
    const float* b_mem     = (const float*)d_in[25];
    float* out = (float*)d_out;

    float *zP, *xpP, *hpP, *gruP, *qP, *kP, *vP, *ctxhP, *ctxP, *ctxpP, *alphP;
    cudaGetSymbolAddress((void**)&zP,    g_z);
    cudaGetSymbolAddress((void**)&xpP,   g_xp);
    cudaGetSymbolAddress((void**)&hpP,   g_hp);
    cudaGetSymbolAddress((void**)&gruP,  g_gru);
    cudaGetSymbolAddress((void**)&qP,    g_q);
    cudaGetSymbolAddress((void**)&kP,    g_k);
    cudaGetSymbolAddress((void**)&vP,    g_v);
    cudaGetSymbolAddress((void**)&ctxhP, g_ctxh);
    cudaGetSymbolAddress((void**)&ctxP,  g_ctx);
    cudaGetSymbolAddress((void**)&ctxpP, g_ctxp);
    cudaGetSymbolAddress((void**)&alphP, g_alph);

    cudaFuncSetAttribute(gemm_tf32<0,false>, cudaFuncAttributeMaxDynamicSharedMemorySize, SMEM_BYTES);
    cudaFuncSetAttribute(gemm_tf32<1,false>, cudaFuncAttributeMaxDynamicSharedMemorySize, SMEM_BYTES);
    cudaFuncSetAttribute(gemm_tf32<2,true >, cudaFuncAttributeMaxDynamicSharedMemorySize, SMEM_BYTES);

    const dim3 blk(256);
    const dim3 gB (4, 64);     // 8192 x 256
    const dim3 gB3(12, 64);    // 8192 x 768
    const dim3 gGate(4, 64);   // 8192 x 256, K=512
    const dim3 gKV(4, 640);    // 81920 x 256

    gemm_tf32<0,false><<<gKV, blk, SMEM_BYTES>>>(memflat, nullptr, Wk, bk, kP, 256, 256, 256);
    gemm_tf32<0,false><<<gKV, blk, SMEM_BYTES>>>(memflat, nullptr, Wv, bv, vP, 256, 256, 256);

    gemm_tf32<0,false><<<gB,  blk, SMEM_BYTES>>>(inputs, nullptr, W_in,   b_in,        zP,  256, 256, 256);
    gemm_tf32<0,false><<<gB3, blk, SMEM_BYTES>>>(zP,     nullptr, gru_k,  gru_b,       xpP, 768, 256, 768);
    gemm_tf32<0,false><<<gB3, blk, SMEM_BYTES>>>(h_prev, nullptr, gru_rk, gru_b + 768, hpP, 768, 256, 768);
    gru_kernel<<<(B_ * D_ + 255) / 256, 256>>>(h_prev);

    gemm_tf32<0,false><<<gB, blk, SMEM_BYTES>>>(gruP, nullptr, Wq, bq, qP, 256, 256, 256);
    attn_kernel<<<(B_ * H_ * 32 + 255) / 256, 256>>>();
    gemm_tf32<0,false><<<gB, blk, SMEM_BYTES>>>(ctxhP, nullptr, Wo, bo, ctxP, 256, 256, 256);
    ln_kernel<<<(B_ * 32 + 255) / 256, 256>>>(ctxP, g_attn, beta_attn, ctxP);

    gemm_tf32<1,false><<<gB,    blk, SMEM_BYTES>>>(ctxP, nullptr, W_ctx,  b_ctx,  ctxpP, 256, 256, 256);
    gemm_tf32<2,true ><<<gGate, blk, SMEM_BYTES>>>(gruP, ctxpP,   W_gate, b_gate, alphP, 256, 512, 256);
    blend_ln_kernel<<<(B_ * 32 + 255) / 256, 256>>>(g_out, beta_out, out);

    memshift_kernel<<<(B_ * 576 + 255) / 256, 256>>>(memflat, out + B_ * D_);
    gemm_tf32<0,false><<<gB, blk, SMEM_BYTES>>>(zP, nullptr, W_mem, b_mem,
                                                out + B_ * D_ + (M_ - 1) * D_, 256, 256, M_ * D_);
}

// round 8
// speedup vs baseline: 1.7291x; 1.1081x over previous
#include <cuda_runtime.h>
#include <math.h>
#include <stdint.h>

#define B_  8192
#define D_  256
#define M_  10
#define H_  4
#define DK_ 64

// ---------------- scratch (device globals; no allocation allowed) ----------
__device__ float g_z   [B_*D_];
__device__ float g_xp  [B_*3*D_];
__device__ float g_hp  [B_*3*D_];
__device__ float g_gru [B_*D_];
__device__ float g_q   [B_*D_];
__device__ float g_k   [B_*M_*D_];
__device__ float g_v   [B_*M_*D_];
__device__ float g_ctxh[B_*D_];
__device__ float g_ctx [B_*D_];
__device__ float g_ctxp[B_*D_];
__device__ float g_alph[B_*D_];

__device__ __forceinline__ float sigf(float x) { return 1.0f / (1.0f + expf(-x)); }

__device__ __forceinline__ void mma_tf32(float acc[4], const uint32_t a[4],
                                         uint32_t b0, uint32_t b1) {
    asm volatile(
        "mma.sync.aligned.m16n8k8.row.col.f32.tf32.tf32.f32 "
        "{%0,%1,%2,%3}, {%4,%5,%6,%7}, {%8,%9}, {%0,%1,%2,%3};"
        : "+f"(acc[0]), "+f"(acc[1]), "+f"(acc[2]), "+f"(acc[3])
        : "r"(a[0]), "r"(a[1]), "r"(a[2]), "r"(a[3]), "r"(b0), "r"(b1));
}

__device__ __forceinline__ void cp16(uint32_t dst, const void* src) {
    asm volatile("cp.async.cg.shared.global [%0], [%1], 16;" :: "r"(dst), "l"(src));
}
__device__ __forceinline__ void cp_commit() {
    asm volatile("cp.async.commit_group;" ::: "memory");
}
template<int N>
__device__ __forceinline__ void cp_wait() {
    asm volatile("cp.async.wait_group %0;" :: "n"(N) : "memory");
}

// ---- smem geometry (words) ----
#define AS_STRIDE 36                       // words per A m-row (32 + 4 pad)
#define ABUF_W    (128 * AS_STRIDE)        // 4608 words
#define BS_STRIDE 72                       // words per B k-row (64 + 8 pad); 72%32==8 -> conflict-free frag LDS
#define BBUF_W    (32 * BS_STRIDE)         // 2304 words
#define STAGE_W   (ABUF_W + BBUF_W)        // 6912 words
#define STAGES    2
#define SMEM_BYTES (STAGES * STAGE_W * 4)  // 55296 -> 4 CTAs/SM

// ---------------- tf32 tensor-core GEMM: C = epi(A @ W + bias) -------------
// Block tile 128x64, BK=32, 256 threads (8 warps, 4m x 2n), warp tile 32x32.
// cp.async gmem->smem (raw f32 bits; HMMA truncates to tf32), 2-stage pipe
// (occupancy 4 CTAs/SM does the latency hiding), A frags via ldmatrix (b16
// trick), B frags via conflict-free scalar LDS.
// EPI: 0=identity, 1=tanh, 2=sigmoid.
// DUAL: A is [A | A2] in K.  ZSEL: blockIdx.z selects {W,bias,C} vs {W2,bias2,C2}
//       and (A vs Az) — for fused K/V and xp/hp launches.
template<int EPI, bool DUAL, bool ZSEL>
__global__ __launch_bounds__(256, 4)
void gemm_tf32(const float* __restrict__ A,  const float* __restrict__ A2,
               const float* __restrict__ Az,
               const float* __restrict__ W,  const float* __restrict__ W2,
               const float* __restrict__ bias, const float* __restrict__ bias2,
               float* __restrict__ C, float* __restrict__ C2,
               int N, int K, int ldc)
{
    extern __shared__ uint32_t sm[];
    const uint32_t sbase = (uint32_t)__cvta_generic_to_shared(sm);

    if (ZSEL && blockIdx.z) {
        if (Az)    A    = Az;
        W    = W2;
        bias = bias2;
        C    = C2;
    }

    const int bm   = blockIdx.y * 128;
    const int bn   = blockIdx.x * 64;
    const int tid  = threadIdx.x;
    const int lane = tid & 31;
    const int wid  = tid >> 5;
    const int wm   = (wid & 3) * 32;
    const int wn   = (wid >> 2) * 32;
    const int g    = lane >> 2;
    const int q    = lane & 3;

    // ldmatrix per-lane address offsets (bytes within an A buffer)
    const int mi = lane >> 3, rr = lane & 7;
    const uint32_t a_off0 = ((wm + (mi & 1) * 8 + rr) * AS_STRIDE + (mi >> 1) * 4) * 4;
    const uint32_t a_off1 = a_off0 + 16 * AS_STRIDE * 4;

    // B fragment base offset (bytes within a B buffer): k-row q, col wn+g
    const uint32_t b_off = (q * BS_STRIDE + wn + g) * 4;

    float acc[2][4][4];
    #pragma unroll
    for (int t = 0; t < 2; t++)
        #pragma unroll
        for (int j = 0; j < 4; j++)
            #pragma unroll
            for (int e = 0; e < 4; e++) acc[t][j][e] = 0.0f;

    // ---- async tile fetch: gmem -> smem stage ----
    auto cp_tile = [&](int k0, int stage) {
        uint32_t abase = sbase + stage * (STAGE_W * 4);
        uint32_t bbase = abase + ABUF_W * 4;
        #pragma unroll
        for (int i = 0; i < 4; i++) {
            int idx = tid + i * 256;
            int row = idx >> 3, c4 = (idx & 7) * 4;
            int gk  = k0 + c4;
            const float* src;
            if (DUAL) {
                src = (gk < 256) ? &A [(size_t)(bm + row) * 256 + gk]
                                 : &A2[(size_t)(bm + row) * 256 + gk - 256];
            } else {
                src = &A[(size_t)(bm + row) * K + gk];
            }
            cp16(abase + (row * AS_STRIDE + c4) * 4, src);
        }
        #pragma unroll
        for (int i = 0; i < 2; i++) {
            int idx = tid + i * 256;
            int kk = idx >> 4, n0 = (idx & 15) * 4;
            cp16(bbase + (kk * BS_STRIDE + n0) * 4, &W[(size_t)(k0 + kk) * N + bn + n0]);
        }
    };

    // ---- fragment load for one k8 step ----
    auto load_frag = [&](uint32_t asb, uint32_t bsb, int kb,
                         uint32_t a0[4], uint32_t a1[4], uint32_t b0[4], uint32_t b1[4]) {
        uint32_t aaddr0 = asb + a_off0 + kb * 32;
        uint32_t aaddr1 = asb + a_off1 + kb * 32;
        asm volatile("ldmatrix.sync.aligned.m8n8.x4.shared.b16 {%0,%1,%2,%3}, [%4];"
            : "=r"(a0[0]), "=r"(a0[1]), "=r"(a0[2]), "=r"(a0[3]) : "r"(aaddr0));
        asm volatile("ldmatrix.sync.aligned.m8n8.x4.shared.b16 {%0,%1,%2,%3}, [%4];"
            : "=r"(a1[0]), "=r"(a1[1]), "=r"(a1[2]), "=r"(a1[3]) : "r"(aaddr1));
        uint32_t bb = bsb + b_off + kb * (8 * BS_STRIDE * 4);
        #pragma unroll
        for (int j = 0; j < 4; j++) {
            asm volatile("ld.shared.b32 %0, [%1];" : "=r"(b0[j]) : "r"(bb + j * 32));
            asm volatile("ld.shared.b32 %0, [%1];" : "=r"(b1[j]) : "r"(bb + j * 32 + 4 * BS_STRIDE * 4));
        }
    };

    auto compute = [&](int stage) {
        const uint32_t asb = sbase + stage * (STAGE_W * 4);
        const uint32_t bsb = asb + ABUF_W * 4;
        uint32_t a0[2][4], a1[2][4], b0[2][4], b1[2][4];
        load_frag(asb, bsb, 0, a0[0], a1[0], b0[0], b1[0]);
        #pragma unroll
        for (int kb = 0; kb < 4; kb++) {
            int cur = kb & 1, nxt = cur ^ 1;
            if (kb < 3) load_frag(asb, bsb, kb + 1, a0[nxt], a1[nxt], b0[nxt], b1[nxt]);
            #pragma unroll
            for (int j = 0; j < 4; j++) {
                mma_tf32(acc[0][j], a0[cur], b0[cur][j], b1[cur][j]);
                mma_tf32(acc[1][j], a1[cur], b0[cur][j], b1[cur][j]);
            }
        }
    };

    const int NIT = K >> 5;

    // 2-stage pipeline: TLP (4 CTAs/SM) hides the per-tile wait.
    cp_tile(0, 0);
    cp_commit();

    for (int it = 0; it < NIT; it++) {
        cp_wait<0>();
        __syncthreads();
        if (it + 1 < NIT) {
            cp_tile((it + 1) * 32, (it + 1) & 1);
            cp_commit();
        }
        compute(it & 1);
        __syncthreads();
    }

    // ---- epilogue: bias + activation, float2 stores ----
    #pragma unroll
    for (int t = 0; t < 2; t++) {
        #pragma unroll
        for (int j = 0; j < 4; j++) {
            int col = bn + wn + j * 8 + 2 * q;
            float b0 = bias[col], b1 = bias[col + 1];
            #pragma unroll
            for (int h = 0; h < 2; h++) {
                int row = bm + wm + t * 16 + g + h * 8;
                float v0 = acc[t][j][2 * h]     + b0;
                float v1 = acc[t][j][2 * h + 1] + b1;
                if (EPI == 1) { v0 = tanhf(v0); v1 = tanhf(v1); }
                if (EPI == 2) { v0 = sigf(v0);  v1 = sigf(v1);  }
                *(float2*)&C[(size_t)row * ldc + col] = make_float2(v0, v1);
            }
        }
    }
}

// ---------------- GRU elementwise (keras reset_after=True) -----------------
__global__ void gru_kernel(const float* __restrict__ h_prev)
{
    int idx = blockIdx.x * blockDim.x + threadIdx.x;
    if (idx >= B_ * D_) return;
    int b = idx >> 8, d = idx & 255;
    const float* xp = g_xp + (size_t)b * 768;
    const float* hp = g_hp + (size_t)b * 768;
    float z  = sigf(xp[d]       + hp[d]);
    float r  = sigf(xp[256 + d] + hp[256 + d]);
    float hc = tanhf(xp[512 + d] + r * hp[512 + d]);
    float h  = h_prev[idx];
    g_gru[idx] = z * h + (1.0f - z) * hc;
}

// ---------------- attention: one warp per (b, h) ----------------------------
__global__ void attn_kernel()
{
    int gw   = (blockIdx.x * blockDim.x + threadIdx.x) >> 5;
    int lane = threadIdx.x & 31;
    if (gw >= B_ * H_) return;
    int b = gw >> 2;
    int h = gw & 3;

    const float* qp = g_q + (size_t)b * D_ + h * DK_;
    float q0 = qp[2 * lane], q1 = qp[2 * lane + 1];

    float sc[M_];
    #pragma unroll
    for (int m = 0; m < M_; m++) {
        const float* kp = g_k + ((size_t)b * M_ + m) * D_ + h * DK_;
        float p = q0 * kp[2 * lane] + q1 * kp[2 * lane + 1];
        #pragma unroll
        for (int o = 16; o > 0; o >>= 1) p += __shfl_xor_sync(0xffffffffu, p, o);
        sc[m] = p * 0.125f;
    }
    float mx = sc[0];
    #pragma unroll
    for (int m = 1; m < M_; m++) mx = fmaxf(mx, sc[m]);
    float sum = 0.0f;
    #pragma unroll
    for (int m = 0; m < M_; m++) { sc[m] = expf(sc[m] - mx); sum += sc[m]; }
    float inv = 1.0f / sum;

    float c0 = 0.0f, c1 = 0.0f;
    #pragma unroll
    for (int m = 0; m < M_; m++) {
        const float* vp = g_v + ((size_t)b * M_ + m) * D_ + h * DK_;
        float a = sc[m] * inv;
        c0 += a * vp[2 * lane];
        c1 += a * vp[2 * lane + 1];
    }
    float* cp = g_ctxh + (size_t)b * D_ + h * DK_;
    cp[2 * lane]     = c0;
    cp[2 * lane + 1] = c1;
}

// ---------------- LayerNorm (warp per row, D = 256) -------------------------
__device__ __forceinline__ void ln_row(const float* x8, int lane,
                                       const float* __restrict__ gm,
                                       const float* __restrict__ bt,
                                       float* __restrict__ yrow)
{
    float s = 0.0f, ss = 0.0f;
    #pragma unroll
    for (int i = 0; i < 8; i++) { s += x8[i]; ss += x8[i] * x8[i]; }
    #pragma unroll
    for (int o = 16; o > 0; o >>= 1) {
        s  += __shfl_xor_sync(0xffffffffu, s,  o);
        ss += __shfl_xor_sync(0xffffffffu, ss, o);
    }
    float mu  = s * (1.0f / 256.0f);
    float var = ss * (1.0f / 256.0f) - mu * mu;
    float inv = rsqrtf(var + 1e-3f);
    float out[8];
    #pragma unroll
    for (int i = 0; i < 8; i++) {
        int d = lane * 8 + i;
        out[i] = (x8[i] - mu) * inv * gm[d] + bt[d];
    }
    *(float4*)(yrow + lane * 8)     = make_float4(out[0], out[1], out[2], out[3]);
    *(float4*)(yrow + lane * 8 + 4) = make_float4(out[4], out[5], out[6], out[7]);
}

__global__ void ln_kernel(const float* __restrict__ x, const float* __restrict__ gm,
                          const float* __restrict__ bt, float* __restrict__ y)
{
    int w    = (blockIdx.x * blockDim.x + threadIdx.x) >> 5;
    int lane = threadIdx.x & 31;
    if (w >= B_) return;
    const float* row = x + (size_t)w * D_;
    float4 v0 = *(const float4*)(row + lane * 8);
    float4 v1 = *(const float4*)(row + lane * 8 + 4);
    float x8[8] = {v0.x, v0.y, v0.z, v0.w, v1.x, v1.y, v1.z, v1.w};
    ln_row(x8, lane, gm, bt, y + (size_t)w * D_);
}

__global__ void blend_ln_kernel(const float* __restrict__ gm,
                                const float* __restrict__ bt,
                                float* __restrict__ out)
{
    int w    = (blockIdx.x * blockDim.x + threadIdx.x) >> 5;
    int lane = threadIdx.x & 31;
    if (w >= B_) return;
    size_t base = (size_t)w * D_ + lane * 8;
    float x8[8];
    #pragma unroll
    for (int i = 0; i < 8; i++) {
        float a = g_alph[base + i];
        x8[i] = (1.0f - a) * g_gru[base + i] + a * g_ctxp[base + i];
    }
    ln_row(x8, lane, gm, bt, out + (size_t)w * D_);
}

// ---------------- memory shift: out_mem[b, 0:9D] = mem[b, D:10D] ------------
__global__ void memshift_kernel(const float* __restrict__ memflat,
                                float* __restrict__ outmem)
{
    const int per = (M_ - 1) * D_ / 4;
    int idx = blockIdx.x * blockDim.x + threadIdx.x;
    if (idx >= B_ * per) return;
    int b = idx / per, j = idx - b * per;
    const float4* src = (const float4*)(memflat + (size_t)b * (M_ * D_) + D_);
    float4*       dst = (float4*)(outmem + (size_t)b * (M_ * D_));
    dst[j] = src[j];
}

// ---------------- host ------------------------------------------------------
extern "C" void kernel_launch(void* const* d_in, const int* in_sizes, int n_in,
                              void* d_out, int out_size)
{
    const float* inputs    = (const float*)d_in[0];
    const float* h_prev    = (const float*)d_in[1];
    const float* memflat   = (const float*)d_in[2];
    const float* W_in      = (const float*)d_in[3];
    const float* b_in      = (const float*)d_in[4];
    const float* gru_k     = (const float*)d_in[5];
    const float* gru_rk    = (const float*)d_in[6];
    const float* gru_b     = (const float*)d_in[7];
    const float* Wq        = (const float*)d_in[8];
    const float* bq        = (const float*)d_in[9];
    const float* Wk        = (const float*)d_in[10];
    const float* bk        = (const float*)d_in[11];
    const float* Wv        = (const float*)d_in[12];
    const float* bv        = (const float*)d_in[13];
    const float* Wo        = (const float*)d_in[14];
    const float* bo        = (const float*)d_in[15];
    const float* g_attn    = (const float*)d_in[16];
    const float* beta_attn = (const float*)d_in[17];
    const float* g_out     = (const float*)d_in[18];
    const float* beta_out  = (const float*)d_in[19];
    const float* W_ctx     = (const float*)d_in[20];
    const float* b_ctx     = (const float*)d_in[21];
    const float* W_gate    = (const float*)d_in[22];
    const float* b_gate    = (const float*)d_in[23];
    const float* W_mem     = (const float*)d_in[24];
    const float* b_mem     = (const float*)d_in[25];
    float* out = (float*)d_out;

    float *zP, *xpP, *hpP, *gruP, *qP, *kP, *vP, *ctxhP, *ctxP, *ctxpP, *alphP;
    cudaGetSymbolAddress((void**)&zP,    g_z);
    cudaGetSymbolAddress((void**)&xpP,   g_xp);
    cudaGetSymbolAddress((void**)&hpP,   g_hp);
    cudaGetSymbolAddress((void**)&gruP,  g_gru);
    cudaGetSymbolAddress((void**)&qP,    g_q);
    cudaGetSymbolAddress((void**)&kP,    g_k);
    cudaGetSymbolAddress((void**)&vP,    g_v);
    cudaGetSymbolAddress((void**)&ctxhP, g_ctxh);
    cudaGetSymbolAddress((void**)&ctxP,  g_ctx);
    cudaGetSymbolAddress((void**)&ctxpP, g_ctxp);
    cudaGetSymbolAddress((void**)&alphP, g_alph);

    cudaFuncSetAttribute(gemm_tf32<0,false,false>, cudaFuncAttributeMaxDynamicSharedMemorySize, SMEM_BYTES);
    cudaFuncSetAttribute(gemm_tf32<0,false,true >, cudaFuncAttributeMaxDynamicSharedMemorySize, SMEM_BYTES);
    cudaFuncSetAttribute(gemm_tf32<1,false,false>, cudaFuncAttributeMaxDynamicSharedMemorySize, SMEM_BYTES);
    cudaFuncSetAttribute(gemm_tf32<2,true ,false>, cudaFuncAttributeMaxDynamicSharedMemorySize, SMEM_BYTES);

    const dim3 blk(256);
    const dim3 gB  (4, 64);        // 8192 x 256
    const dim3 gKV (4, 640, 2);    // 81920 x 256, z: K | V
    const dim3 gXH (12, 64, 2);    // 8192 x 768,  z: xp | hp

    // K & V projections fused in one launch (z selects weights/outputs)
    gemm_tf32<0,false,true><<<gKV, blk, SMEM_BYTES>>>(
        memflat, nullptr, nullptr, Wk, Wv, bk, bv, kP, vP, 256, 256, 256);

    // z_t
    gemm_tf32<0,false,false><<<gB, blk, SMEM_BYTES>>>(
        inputs, nullptr, nullptr, W_in, nullptr, b_in, nullptr, zP, nullptr, 256, 256, 256);

    // xp & hp fused (z selects A too)
    gemm_tf32<0,false,true><<<gXH, blk, SMEM_BYTES>>>(
        zP, nullptr, h_prev, gru_k, gru_rk, gru_b, gru_b + 768, xpP, hpP, 768, 256, 768);
    gru_kernel<<<(B_ * D_ + 255) / 256, 256>>>(h_prev);

    // attention
    gemm_tf32<0,false,false><<<gB, blk, SMEM_BYTES>>>(
        gruP, nullptr, nullptr, Wq, nullptr, bq, nullptr, qP, nullptr, 256, 256, 256);
    attn_kernel<<<(B_ * H_ * 32 + 255) / 256, 256>>>();
    gemm_tf32<0,false,false><<<gB, blk, SMEM_BYTES>>>(
        ctxhP, nullptr, nullptr, Wo, nullptr, bo, nullptr, ctxP, nullptr, 256, 256, 256);
    ln_kernel<<<(B_ * 32 + 255) / 256, 256>>>(ctxP, g_attn, beta_attn, ctxP);

    // ctx_p, gate, blend+LN -> h_corr
    gemm_tf32<1,false,false><<<gB, blk, SMEM_BYTES>>>(
        ctxP, nullptr, nullptr, W_ctx, nullptr, b_ctx, nullptr, ctxpP, nullptr, 256, 256, 256);
    gemm_tf32<2,true,false><<<gB, blk, SMEM_BYTES>>>(
        gruP, ctxpP, nullptr, W_gate, nullptr, b_gate, nullptr, alphP, nullptr, 256, 512, 256);
    blend_ln_kernel<<<(B_ * 32 + 255) / 256, 256>>>(g_out, beta_out, out);

    // memory write: shifted copy + new entry in last slot
    memshift_kernel<<<(B_ * 576 + 255) / 256, 256>>>(memflat, out + B_ * D_);
    gemm_tf32<0,false,false><<<gB, blk, SMEM_BYTES>>>(
        zP, nullptr, nullptr, W_mem, nullptr, b_mem, nullptr,
        out + B_ * D_ + (M_ - 1) * D_, nullptr, 256, 256, M_ * D_);
}